// round 1
// baseline (speedup 1.0000x reference)
#include <cuda_runtime.h>
#include <math.h>

// Problem constants
#define BB 2
#define LL 2048
#define DD 1024
#define NS 16        // D_STATE
#define RK 64        // DT_RANK
#define NE 96        // RK + 2*NS
#define NROW (BB*LL) // 4096
#define NC 32        // chunks per sequence
#define LC (LL/NC)   // 64 steps per chunk

// Scratch (device globals; no allocations allowed)
__device__ float g_xp[NROW * NE];        // [row][96]  : dr | B | C
__device__ float g_delta[NROW * DD];     // [row][d]
__device__ float g_ap[BB * NC * DD * NS];
__device__ float g_ho[BB * NC * DD * NS];
__device__ float g_hi[BB * NC * DD * NS];

__device__ __forceinline__ float ex2f_fast(float x) {
    float r;
    asm("ex2.approx.f32 %0, %1;" : "=f"(r) : "f"(x));
    return r;
}

// ---------------------------------------------------------------------------
// GEMM1: xp[row, e] = sum_k x[row, k] * Wx[e, k]    (M=4096, N=96, K=1024)
// Tile: 32 rows x 96 cols, BK=32, 256 threads, micro 4x3
// ---------------------------------------------------------------------------
__global__ void __launch_bounds__(256) k_gemm1(const float* __restrict__ x,
                                               const float* __restrict__ wx) {
    __shared__ float xs[32][33];
    __shared__ float ws[96][33];
    const int t = threadIdx.x;
    const int row0 = blockIdx.x * 32;
    const int trow = t >> 5;   // 0..7
    const int tcol = t & 31;   // 0..31

    float acc[4][3] = {};

    for (int k0 = 0; k0 < 1024; k0 += 32) {
        // load x tile: 32x32 = 1024 floats, 256 float4
        {
            int r = t >> 3;
            int kk = (t & 7) << 2;
            float4 v = *(const float4*)(x + (size_t)(row0 + r) * DD + k0 + kk);
            xs[r][kk] = v.x; xs[r][kk + 1] = v.y; xs[r][kk + 2] = v.z; xs[r][kk + 3] = v.w;
        }
        // load w tile: 96x32 = 3072 floats
        #pragma unroll
        for (int q = 0; q < 3; ++q) {
            int idx = t + q * 256;
            int r = idx >> 3;
            int kk = (idx & 7) << 2;
            float4 v = *(const float4*)(wx + (size_t)r * DD + k0 + kk);
            ws[r][kk] = v.x; ws[r][kk + 1] = v.y; ws[r][kk + 2] = v.z; ws[r][kk + 3] = v.w;
        }
        __syncthreads();

        #pragma unroll
        for (int kk = 0; kk < 32; ++kk) {
            float a0 = xs[trow * 4 + 0][kk];
            float a1 = xs[trow * 4 + 1][kk];
            float a2 = xs[trow * 4 + 2][kk];
            float a3 = xs[trow * 4 + 3][kk];
            float b0 = ws[tcol][kk];
            float b1 = ws[tcol + 32][kk];
            float b2 = ws[tcol + 64][kk];
            acc[0][0] = fmaf(a0, b0, acc[0][0]);
            acc[0][1] = fmaf(a0, b1, acc[0][1]);
            acc[0][2] = fmaf(a0, b2, acc[0][2]);
            acc[1][0] = fmaf(a1, b0, acc[1][0]);
            acc[1][1] = fmaf(a1, b1, acc[1][1]);
            acc[1][2] = fmaf(a1, b2, acc[1][2]);
            acc[2][0] = fmaf(a2, b0, acc[2][0]);
            acc[2][1] = fmaf(a2, b1, acc[2][1]);
            acc[2][2] = fmaf(a2, b2, acc[2][2]);
            acc[3][0] = fmaf(a3, b0, acc[3][0]);
            acc[3][1] = fmaf(a3, b1, acc[3][1]);
            acc[3][2] = fmaf(a3, b2, acc[3][2]);
        }
        __syncthreads();
    }

    #pragma unroll
    for (int i = 0; i < 4; ++i)
        #pragma unroll
        for (int j = 0; j < 3; ++j)
            g_xp[(size_t)(row0 + trow * 4 + i) * NE + tcol + 32 * j] = acc[i][j];
}

// ---------------------------------------------------------------------------
// GEMM2: delta[row, d] = softplus( sum_r dr[row, r] * Wdt[d, r] + bias[d] )
// (M=4096, N=1024, K=64). Tile 64 rows x 64 cols, single K pass, micro 8x2.
// ---------------------------------------------------------------------------
__global__ void __launch_bounds__(256) k_gemm2(const float* __restrict__ wdt,
                                               const float* __restrict__ bias) {
    __shared__ float ds[64][64];    // [row][k]
    __shared__ float ws2[64][64];   // [k][col]  (transposed store)
    const int t = threadIdx.x;
    const int row0 = blockIdx.y * 64;
    const int col0 = blockIdx.x * 64;

    // load dr tile: 64 rows x 64 k
    #pragma unroll
    for (int q = 0; q < 4; ++q) {
        int idx = t + q * 256;
        int r = idx >> 4;
        int kk = (idx & 15) << 2;
        float4 v = *(const float4*)(g_xp + (size_t)(row0 + r) * NE + kk);
        *(float4*)&ds[r][kk] = v;
    }
    // load Wdt tile transposed: cols 64 x k 64
    #pragma unroll
    for (int q = 0; q < 4; ++q) {
        int idx = t + q * 256;
        int r = idx >> 4;               // col index 0..63
        int kk = (idx & 15) << 2;
        float4 v = *(const float4*)(wdt + (size_t)(col0 + r) * RK + kk);
        ws2[kk][r] = v.x; ws2[kk + 1][r] = v.y; ws2[kk + 2][r] = v.z; ws2[kk + 3][r] = v.w;
    }
    __syncthreads();

    const int trow = t >> 5;  // 0..7 -> rows trow*8 + i
    const int tcol = t & 31;  // cols tcol + 32*j

    float acc[8][2] = {};
    #pragma unroll 16
    for (int kk = 0; kk < 64; ++kk) {
        float b0 = ws2[kk][tcol];
        float b1 = ws2[kk][tcol + 32];
        #pragma unroll
        for (int i = 0; i < 8; ++i) {
            float a = ds[trow * 8 + i][kk];
            acc[i][0] = fmaf(a, b0, acc[i][0]);
            acc[i][1] = fmaf(a, b1, acc[i][1]);
        }
    }

    #pragma unroll
    for (int i = 0; i < 8; ++i) {
        #pragma unroll
        for (int j = 0; j < 2; ++j) {
            int row = row0 + trow * 8 + i;
            int col = col0 + tcol + 32 * j;
            float z = acc[i][j] + bias[col];
            float sp = (z > 15.0f) ? z : log1pf(__expf(z));
            g_delta[(size_t)row * DD + col] = sp;
        }
    }
}

// ---------------------------------------------------------------------------
// Scan pass 1: per (b, d, chunk) thread, h starts at 0; record prod(dA) and h_out
// ---------------------------------------------------------------------------
__global__ void __launch_bounds__(128) k_scan1(const float* __restrict__ x,
                                               const float* __restrict__ A_log) {
    const int d = blockIdx.x * 128 + threadIdx.x;
    const int c = blockIdx.y;
    const int b = blockIdx.z;

    float A2[NS];
    #pragma unroll
    for (int q = 0; q < 4; ++q) {
        float4 v = *(const float4*)(A_log + (size_t)d * NS + q * 4);
        A2[q * 4 + 0] = -__expf(v.x) * 1.4426950408889634f;
        A2[q * 4 + 1] = -__expf(v.y) * 1.4426950408889634f;
        A2[q * 4 + 2] = -__expf(v.z) * 1.4426950408889634f;
        A2[q * 4 + 3] = -__expf(v.w) * 1.4426950408889634f;
    }

    float h[NS], ap[NS];
    #pragma unroll
    for (int n = 0; n < NS; ++n) { h[n] = 0.0f; ap[n] = 1.0f; }

    const int rbase = b * LL + c * LC;
    for (int s = 0; s < LC; ++s) {
        const int row = rbase + s;
        const float dl = g_delta[(size_t)row * DD + d];
        const float xv = x[(size_t)row * DD + d];
        const float dx = dl * xv;
        const float4* Bp = (const float4*)(g_xp + (size_t)row * NE + RK);
        float Bv[NS];
        #pragma unroll
        for (int q = 0; q < 4; ++q) {
            float4 v = __ldg(Bp + q);
            Bv[q * 4 + 0] = v.x; Bv[q * 4 + 1] = v.y; Bv[q * 4 + 2] = v.z; Bv[q * 4 + 3] = v.w;
        }
        #pragma unroll
        for (int n = 0; n < NS; ++n) {
            float a = ex2f_fast(dl * A2[n]);
            h[n] = fmaf(a, h[n], dx * Bv[n]);
            ap[n] *= a;
        }
    }

    const size_t off = ((size_t)(b * NC + c) * DD + d) * NS;
    #pragma unroll
    for (int q = 0; q < 4; ++q) {
        *(float4*)(g_ho + off + q * 4) = make_float4(h[q*4], h[q*4+1], h[q*4+2], h[q*4+3]);
        *(float4*)(g_ap + off + q * 4) = make_float4(ap[q*4], ap[q*4+1], ap[q*4+2], ap[q*4+3]);
    }
}

// ---------------------------------------------------------------------------
// Combine: sequential over chunks (per (b,d,n) thread), produce h_in per chunk
// ---------------------------------------------------------------------------
__global__ void __launch_bounds__(256) k_comb() {
    const int gid = blockIdx.x * 256 + threadIdx.x;     // 0 .. BB*DD*NS-1
    const int b = gid / (DD * NS);
    const int rem = gid % (DD * NS);                    // d*NS + n
    float h = 0.0f;
    #pragma unroll
    for (int c = 0; c < NC; ++c) {
        const size_t off = (size_t)(b * NC + c) * DD * NS + rem;
        g_hi[off] = h;
        h = fmaf(g_ap[off], h, g_ho[off]);
    }
}

// ---------------------------------------------------------------------------
// Scan pass 2: replay with correct h_in, emit y = sum_n h[n]*C[n] + x*D
// ---------------------------------------------------------------------------
__global__ void __launch_bounds__(128) k_scan2(const float* __restrict__ x,
                                               const float* __restrict__ A_log,
                                               const float* __restrict__ Dw,
                                               float* __restrict__ out) {
    const int d = blockIdx.x * 128 + threadIdx.x;
    const int c = blockIdx.y;
    const int b = blockIdx.z;

    float A2[NS];
    #pragma unroll
    for (int q = 0; q < 4; ++q) {
        float4 v = *(const float4*)(A_log + (size_t)d * NS + q * 4);
        A2[q * 4 + 0] = -__expf(v.x) * 1.4426950408889634f;
        A2[q * 4 + 1] = -__expf(v.y) * 1.4426950408889634f;
        A2[q * 4 + 2] = -__expf(v.z) * 1.4426950408889634f;
        A2[q * 4 + 3] = -__expf(v.w) * 1.4426950408889634f;
    }
    const float Dv = Dw[d];

    float h[NS];
    {
        const size_t off = ((size_t)(b * NC + c) * DD + d) * NS;
        #pragma unroll
        for (int q = 0; q < 4; ++q) {
            float4 v = *(const float4*)(g_hi + off + q * 4);
            h[q * 4 + 0] = v.x; h[q * 4 + 1] = v.y; h[q * 4 + 2] = v.z; h[q * 4 + 3] = v.w;
        }
    }

    const int rbase = b * LL + c * LC;
    for (int s = 0; s < LC; ++s) {
        const int row = rbase + s;
        const float dl = g_delta[(size_t)row * DD + d];
        const float xv = x[(size_t)row * DD + d];
        const float dx = dl * xv;
        const float4* Bp = (const float4*)(g_xp + (size_t)row * NE + RK);
        float Bv[NS], Cv[NS];
        #pragma unroll
        for (int q = 0; q < 4; ++q) {
            float4 v = __ldg(Bp + q);
            Bv[q * 4 + 0] = v.x; Bv[q * 4 + 1] = v.y; Bv[q * 4 + 2] = v.z; Bv[q * 4 + 3] = v.w;
        }
        #pragma unroll
        for (int q = 0; q < 4; ++q) {
            float4 v = __ldg(Bp + 4 + q);  // C starts at offset 80 = 64+16
            Cv[q * 4 + 0] = v.x; Cv[q * 4 + 1] = v.y; Cv[q * 4 + 2] = v.z; Cv[q * 4 + 3] = v.w;
        }
        float y = xv * Dv;
        #pragma unroll
        for (int n = 0; n < NS; ++n) {
            float a = ex2f_fast(dl * A2[n]);
            h[n] = fmaf(a, h[n], dx * Bv[n]);
            y = fmaf(h[n], Cv[n], y);
        }
        out[(size_t)row * DD + d] = y;
    }
}

// ---------------------------------------------------------------------------
extern "C" void kernel_launch(void* const* d_in, const int* in_sizes, int n_in,
                              void* d_out, int out_size) {
    const float* x     = (const float*)d_in[0];
    const float* A_log = (const float*)d_in[1];
    const float* Dw    = (const float*)d_in[2];
    const float* wx    = (const float*)d_in[3];
    const float* wdt   = (const float*)d_in[4];
    const float* bias  = (const float*)d_in[5];
    float* out = (float*)d_out;

    k_gemm1<<<NROW / 32, 256>>>(x, wx);

    dim3 g2(DD / 64, NROW / 64);
    k_gemm2<<<g2, 256>>>(wdt, bias);

    dim3 gs(DD / 128, NC, BB);
    k_scan1<<<gs, 128>>>(x, A_log);

    k_comb<<<(BB * DD * NS) / 256, 256>>>();

    k_scan2<<<gs, 128>>>(x, A_log, Dw, out);
}

// round 2
// speedup vs baseline: 1.0604x; 1.0604x over previous
#include <cuda_runtime.h>
#include <math.h>

// Problem constants
#define BB 2
#define LL 2048
#define DD 1024
#define NS 16        // D_STATE
#define RK 64        // DT_RANK
#define NE 96        // RK + 2*NS
#define NROW (BB*LL) // 4096
#define NC 64        // chunks per sequence
#define LC (LL/NC)   // 32 steps per chunk
#define DDNS (DD*NS) // 16384

// Scratch (device globals; no allocations allowed)
__device__ float g_xp[NROW * NE];        // [row][96]  : dr | B | C
__device__ float g_delta[NROW * DD];     // [row][d]
__device__ float g_ap[BB * NC * DDNS];
__device__ float g_ho[BB * NC * DDNS];
__device__ float g_hi[BB * NC * DDNS];

__device__ __forceinline__ float ex2f_fast(float x) {
    float r;
    asm("ex2.approx.f32 %0, %1;" : "=f"(r) : "f"(x));
    return r;
}

// ---------------------------------------------------------------------------
// GEMM1: xp[row, e] = sum_k x[row, k] * Wx[e, k]    (M=4096, N=96, K=1024)
// Tile: 32 rows x 96 cols, BK=32, 256 threads, micro 4x3.
// k-unroll 4 with float4 LDS on xs; ws stored transposed [k][col].
// Register-prefetch double buffering on the global loads.
// ---------------------------------------------------------------------------
__global__ void __launch_bounds__(256) k_gemm1(const float* __restrict__ x,
                                               const float* __restrict__ wx) {
    __shared__ float xs[32][36];     // [row][k], rows 144B (16B aligned)
    __shared__ float ws[32][100];    // [k][col], conflict-free col reads

    const int t = threadIdx.x;
    const int row0 = blockIdx.x * 32;
    const int trow = t >> 5;   // 0..7 (warp-uniform)
    const int tcol = t & 31;   // 0..31

    // global load indices
    const int xr = t >> 3;            // 0..31
    const int xk = (t & 7) << 2;      // 0,4,..,28

    float4 xa;
    float4 wa[3];
    // prefetch first tile
    xa = *(const float4*)(x + (size_t)(row0 + xr) * DD + 0 + xk);
    #pragma unroll
    for (int q = 0; q < 3; ++q) {
        int idx = t + q * 256;
        int r = idx >> 3;
        int kk = (idx & 7) << 2;
        wa[q] = *(const float4*)(wx + (size_t)r * DD + 0 + kk);
    }

    float acc[4][3] = {};

    for (int k0 = 0; k0 < 1024; k0 += 32) {
        // commit prefetched regs to smem
        *(float4*)&xs[xr][xk] = xa;
        #pragma unroll
        for (int q = 0; q < 3; ++q) {
            int idx = t + q * 256;
            int r = idx >> 3;
            int kk = (idx & 7) << 2;
            ws[kk + 0][r] = wa[q].x;
            ws[kk + 1][r] = wa[q].y;
            ws[kk + 2][r] = wa[q].z;
            ws[kk + 3][r] = wa[q].w;
        }
        __syncthreads();

        // prefetch next tile
        if (k0 + 32 < 1024) {
            xa = *(const float4*)(x + (size_t)(row0 + xr) * DD + (k0 + 32) + xk);
            #pragma unroll
            for (int q = 0; q < 3; ++q) {
                int idx = t + q * 256;
                int r = idx >> 3;
                int kk = (idx & 7) << 2;
                wa[q] = *(const float4*)(wx + (size_t)r * DD + (k0 + 32) + kk);
            }
        }

        // inner product over this K tile
        #pragma unroll
        for (int kk = 0; kk < 32; kk += 4) {
            float4 a[4];
            #pragma unroll
            for (int i = 0; i < 4; ++i)
                a[i] = *(const float4*)&xs[trow * 4 + i][kk];

            #pragma unroll
            for (int j = 0; j < 4; ++j) {
                float b0 = ws[kk + j][tcol];
                float b1 = ws[kk + j][tcol + 32];
                float b2 = ws[kk + j][tcol + 64];
                #pragma unroll
                for (int i = 0; i < 4; ++i) {
                    float av = (j == 0) ? a[i].x : (j == 1) ? a[i].y : (j == 2) ? a[i].z : a[i].w;
                    acc[i][0] = fmaf(av, b0, acc[i][0]);
                    acc[i][1] = fmaf(av, b1, acc[i][1]);
                    acc[i][2] = fmaf(av, b2, acc[i][2]);
                }
            }
        }
        __syncthreads();
    }

    #pragma unroll
    for (int i = 0; i < 4; ++i)
        #pragma unroll
        for (int j = 0; j < 3; ++j)
            g_xp[(size_t)(row0 + trow * 4 + i) * NE + tcol + 32 * j] = acc[i][j];
}

// ---------------------------------------------------------------------------
// GEMM2: delta[row, d] = softplus( sum_r dr[row, r] * Wdt[d, r] + bias[d] )
// (M=4096, N=1024, K=64). Tile 64 rows x 64 cols, single K pass, micro 8x2.
// ---------------------------------------------------------------------------
__global__ void __launch_bounds__(256) k_gemm2(const float* __restrict__ wdt,
                                               const float* __restrict__ bias) {
    __shared__ float ds[64][64];    // [row][k]
    __shared__ float ws2[64][64];   // [k][col]  (transposed store)
    const int t = threadIdx.x;
    const int row0 = blockIdx.y * 64;
    const int col0 = blockIdx.x * 64;

    #pragma unroll
    for (int q = 0; q < 4; ++q) {
        int idx = t + q * 256;
        int r = idx >> 4;
        int kk = (idx & 15) << 2;
        float4 v = *(const float4*)(g_xp + (size_t)(row0 + r) * NE + kk);
        *(float4*)&ds[r][kk] = v;
    }
    #pragma unroll
    for (int q = 0; q < 4; ++q) {
        int idx = t + q * 256;
        int r = idx >> 4;               // col index 0..63
        int kk = (idx & 15) << 2;
        float4 v = *(const float4*)(wdt + (size_t)(col0 + r) * RK + kk);
        ws2[kk][r] = v.x; ws2[kk + 1][r] = v.y; ws2[kk + 2][r] = v.z; ws2[kk + 3][r] = v.w;
    }
    __syncthreads();

    const int trow = t >> 5;  // 0..7 -> rows trow*8 + i
    const int tcol = t & 31;  // cols tcol + 32*j

    float acc[8][2] = {};
    #pragma unroll 16
    for (int kk = 0; kk < 64; ++kk) {
        float b0 = ws2[kk][tcol];
        float b1 = ws2[kk][tcol + 32];
        #pragma unroll
        for (int i = 0; i < 8; ++i) {
            float a = ds[trow * 8 + i][kk];
            acc[i][0] = fmaf(a, b0, acc[i][0]);
            acc[i][1] = fmaf(a, b1, acc[i][1]);
        }
    }

    #pragma unroll
    for (int i = 0; i < 8; ++i) {
        #pragma unroll
        for (int j = 0; j < 2; ++j) {
            int row = row0 + trow * 8 + i;
            int col = col0 + tcol + 32 * j;
            float z = acc[i][j] + bias[col];
            float sp = (z > 15.0f) ? z : log1pf(__expf(z));
            g_delta[(size_t)row * DD + col] = sp;
        }
    }
}

// ---------------------------------------------------------------------------
// Scan pass 1: per (b, d, chunk) thread, h starts at 0; record prod(dA) and h_out
// prod(dA[n]) == exp2(A2[n] * sum(delta))  -> 16 fewer FMA per step
// ---------------------------------------------------------------------------
__global__ void __launch_bounds__(128) k_scan1(const float* __restrict__ x,
                                               const float* __restrict__ A_log) {
    const int d = blockIdx.x * 128 + threadIdx.x;
    const int c = blockIdx.y;
    const int b = blockIdx.z;

    float A2[NS];
    #pragma unroll
    for (int q = 0; q < 4; ++q) {
        float4 v = *(const float4*)(A_log + (size_t)d * NS + q * 4);
        A2[q * 4 + 0] = -__expf(v.x) * 1.4426950408889634f;
        A2[q * 4 + 1] = -__expf(v.y) * 1.4426950408889634f;
        A2[q * 4 + 2] = -__expf(v.z) * 1.4426950408889634f;
        A2[q * 4 + 3] = -__expf(v.w) * 1.4426950408889634f;
    }

    float h[NS];
    #pragma unroll
    for (int n = 0; n < NS; ++n) h[n] = 0.0f;
    float sdl = 0.0f;

    const int rbase = b * LL + c * LC;
    for (int s = 0; s < LC; ++s) {
        const int row = rbase + s;
        const float dl = g_delta[(size_t)row * DD + d];
        const float xv = x[(size_t)row * DD + d];
        const float dx = dl * xv;
        sdl += dl;
        const float4* Bp = (const float4*)(g_xp + (size_t)row * NE + RK);
        float Bv[NS];
        #pragma unroll
        for (int q = 0; q < 4; ++q) {
            float4 v = __ldg(Bp + q);
            Bv[q * 4 + 0] = v.x; Bv[q * 4 + 1] = v.y; Bv[q * 4 + 2] = v.z; Bv[q * 4 + 3] = v.w;
        }
        #pragma unroll
        for (int n = 0; n < NS; ++n) {
            float a = ex2f_fast(dl * A2[n]);
            h[n] = fmaf(a, h[n], dx * Bv[n]);
        }
    }

    const size_t off = ((size_t)(b * NC + c) * DD + d) * NS;
    #pragma unroll
    for (int q = 0; q < 4; ++q) {
        *(float4*)(g_ho + off + q * 4) = make_float4(h[q*4], h[q*4+1], h[q*4+2], h[q*4+3]);
        float4 apv;
        apv.x = ex2f_fast(A2[q*4+0] * sdl);
        apv.y = ex2f_fast(A2[q*4+1] * sdl);
        apv.z = ex2f_fast(A2[q*4+2] * sdl);
        apv.w = ex2f_fast(A2[q*4+3] * sdl);
        *(float4*)(g_ap + off + q * 4) = apv;
    }
}

// ---------------------------------------------------------------------------
// Combine: sequential over chunks per (b,d,n) thread, batched loads for MLP.
// ---------------------------------------------------------------------------
__global__ void __launch_bounds__(128) k_comb() {
    const int gid = blockIdx.x * 128 + threadIdx.x;     // 0 .. BB*DDNS-1
    const int b = gid >> 14;            // DDNS = 16384
    const int rem = gid & (DDNS - 1);   // d*NS + n
    float h = 0.0f;
    #pragma unroll
    for (int c0 = 0; c0 < NC; c0 += 16) {
        float av[16], hv[16];
        #pragma unroll
        for (int j = 0; j < 16; ++j) {
            const size_t off = (size_t)(b * NC + c0 + j) * DDNS + rem;
            av[j] = g_ap[off];
            hv[j] = g_ho[off];
        }
        #pragma unroll
        for (int j = 0; j < 16; ++j) {
            const size_t off = (size_t)(b * NC + c0 + j) * DDNS + rem;
            g_hi[off] = h;
            h = fmaf(av[j], h, hv[j]);
        }
    }
}

// ---------------------------------------------------------------------------
// Scan pass 2: replay with correct h_in, emit y = sum_n h[n]*C[n] + x*D
// ---------------------------------------------------------------------------
__global__ void __launch_bounds__(128) k_scan2(const float* __restrict__ x,
                                               const float* __restrict__ A_log,
                                               const float* __restrict__ Dw,
                                               float* __restrict__ out) {
    const int d = blockIdx.x * 128 + threadIdx.x;
    const int c = blockIdx.y;
    const int b = blockIdx.z;

    float A2[NS];
    #pragma unroll
    for (int q = 0; q < 4; ++q) {
        float4 v = *(const float4*)(A_log + (size_t)d * NS + q * 4);
        A2[q * 4 + 0] = -__expf(v.x) * 1.4426950408889634f;
        A2[q * 4 + 1] = -__expf(v.y) * 1.4426950408889634f;
        A2[q * 4 + 2] = -__expf(v.z) * 1.4426950408889634f;
        A2[q * 4 + 3] = -__expf(v.w) * 1.4426950408889634f;
    }
    const float Dv = Dw[d];

    float h[NS];
    {
        const size_t off = ((size_t)(b * NC + c) * DD + d) * NS;
        #pragma unroll
        for (int q = 0; q < 4; ++q) {
            float4 v = *(const float4*)(g_hi + off + q * 4);
            h[q * 4 + 0] = v.x; h[q * 4 + 1] = v.y; h[q * 4 + 2] = v.z; h[q * 4 + 3] = v.w;
        }
    }

    const int rbase = b * LL + c * LC;
    for (int s = 0; s < LC; ++s) {
        const int row = rbase + s;
        const float dl = g_delta[(size_t)row * DD + d];
        const float xv = x[(size_t)row * DD + d];
        const float dx = dl * xv;
        const float4* Bp = (const float4*)(g_xp + (size_t)row * NE + RK);
        float Bv[NS], Cv[NS];
        #pragma unroll
        for (int q = 0; q < 4; ++q) {
            float4 v = __ldg(Bp + q);
            Bv[q * 4 + 0] = v.x; Bv[q * 4 + 1] = v.y; Bv[q * 4 + 2] = v.z; Bv[q * 4 + 3] = v.w;
        }
        #pragma unroll
        for (int q = 0; q < 4; ++q) {
            float4 v = __ldg(Bp + 4 + q);  // C at offset 80
            Cv[q * 4 + 0] = v.x; Cv[q * 4 + 1] = v.y; Cv[q * 4 + 2] = v.z; Cv[q * 4 + 3] = v.w;
        }
        float y = xv * Dv;
        #pragma unroll
        for (int n = 0; n < NS; ++n) {
            float a = ex2f_fast(dl * A2[n]);
            h[n] = fmaf(a, h[n], dx * Bv[n]);
            y = fmaf(h[n], Cv[n], y);
        }
        out[(size_t)row * DD + d] = y;
    }
}

// ---------------------------------------------------------------------------
extern "C" void kernel_launch(void* const* d_in, const int* in_sizes, int n_in,
                              void* d_out, int out_size) {
    const float* x     = (const float*)d_in[0];
    const float* A_log = (const float*)d_in[1];
    const float* Dw    = (const float*)d_in[2];
    const float* wx    = (const float*)d_in[3];
    const float* wdt   = (const float*)d_in[4];
    const float* bias  = (const float*)d_in[5];
    float* out = (float*)d_out;

    k_gemm1<<<NROW / 32, 256>>>(x, wx);

    dim3 g2(DD / 64, NROW / 64);
    k_gemm2<<<g2, 256>>>(wdt, bias);

    dim3 gs(DD / 128, NC, BB);
    k_scan1<<<gs, 128>>>(x, A_log);

    k_comb<<<(BB * DDNS) / 128, 128>>>();

    k_scan2<<<gs, 128>>>(x, A_log, Dw, out);
}

// round 3
// speedup vs baseline: 1.1705x; 1.1039x over previous
#include <cuda_runtime.h>
#include <math.h>

// Problem constants
#define BB 2
#define LL 2048
#define DD 1024
#define NS 16        // D_STATE
#define RK 64        // DT_RANK
#define NE 96        // RK + 2*NS
#define NROW (BB*LL) // 4096
#define NC 64        // chunks per sequence
#define LC (LL/NC)   // 32 steps per chunk
#define DDNS (DD*NS) // 16384

typedef unsigned long long ull;

// Scratch (device globals; no allocations allowed)
__device__ float g_xp[NROW * NE];        // [row][96]  : dr | B | C
__device__ float g_delta[NROW * DD];     // [row][d]
__device__ float g_ap[BB * NC * DDNS];
__device__ float g_ho[BB * NC * DDNS];
__device__ float g_hi[BB * NC * DDNS];

__device__ __forceinline__ float ex2f_fast(float x) {
    float r;
    asm("ex2.approx.f32 %0, %1;" : "=f"(r) : "f"(x));
    return r;
}
__device__ __forceinline__ float lg2f_fast(float x) {
    float r;
    asm("lg2.approx.f32 %0, %1;" : "=f"(r) : "f"(x));
    return r;
}
// packed fp32 helpers (Blackwell f32x2 pipe)
__device__ __forceinline__ ull f2p(float lo, float hi) {
    ull r;
    asm("mov.b64 %0, {%1, %2};" : "=l"(r) : "f"(lo), "f"(hi));
    return r;
}
__device__ __forceinline__ void p2f(ull p, float& lo, float& hi) {
    asm("mov.b64 {%0, %1}, %2;" : "=f"(lo), "=f"(hi) : "l"(p));
}
__device__ __forceinline__ ull fma2p(ull a, ull b, ull c) {
    ull d;
    asm("fma.rn.f32x2 %0, %1, %2, %3;" : "=l"(d) : "l"(a), "l"(b), "l"(c));
    return d;
}
__device__ __forceinline__ ull mul2p(ull a, ull b) {
    ull d;
    asm("mul.rn.f32x2 %0, %1, %2;" : "=l"(d) : "l"(a), "l"(b));
    return d;
}

// ---------------------------------------------------------------------------
// GEMM1: xp[row, e] = sum_k x[row, k] * Wx[e, k]    (M=4096, N=96, K=1024)
// Tile 32 rows x 96 cols, BK=32, 256 threads, micro 4x3, f32x2-packed rows.
// xs stored transposed [k][row] so row-pairs load as one b64 (broadcast).
// ---------------------------------------------------------------------------
__global__ void __launch_bounds__(256) k_gemm1(const float* __restrict__ x,
                                               const float* __restrict__ wx) {
    __shared__ float xs_t[32][36];   // [k][row], 144B rows (8B multiple)
    __shared__ float ws[32][100];    // [k][col]

    const int t = threadIdx.x;
    const int row0 = blockIdx.x * 32;
    const int trow4 = (t >> 5) * 4;  // warp-uniform row group
    const int tcol = t & 31;

    const int xr = t >> 3;            // 0..31
    const int xk = (t & 7) << 2;      // 0,4,..,28

    float4 xa;
    float4 wa[3];
    xa = *(const float4*)(x + (size_t)(row0 + xr) * DD + xk);
    #pragma unroll
    for (int q = 0; q < 3; ++q) {
        int idx = t + q * 256;
        int r = idx >> 3;
        int kk = (idx & 7) << 2;
        wa[q] = *(const float4*)(wx + (size_t)r * DD + kk);
    }

    ull acc2[2][3] = {};

    for (int k0 = 0; k0 < 1024; k0 += 32) {
        // commit prefetched regs to smem (x transposed)
        xs_t[xk + 0][xr] = xa.x;
        xs_t[xk + 1][xr] = xa.y;
        xs_t[xk + 2][xr] = xa.z;
        xs_t[xk + 3][xr] = xa.w;
        #pragma unroll
        for (int q = 0; q < 3; ++q) {
            int idx = t + q * 256;
            int r = idx >> 3;
            int kk = (idx & 7) << 2;
            ws[kk + 0][r] = wa[q].x;
            ws[kk + 1][r] = wa[q].y;
            ws[kk + 2][r] = wa[q].z;
            ws[kk + 3][r] = wa[q].w;
        }
        __syncthreads();

        if (k0 + 32 < 1024) {
            xa = *(const float4*)(x + (size_t)(row0 + xr) * DD + (k0 + 32) + xk);
            #pragma unroll
            for (int q = 0; q < 3; ++q) {
                int idx = t + q * 256;
                int r = idx >> 3;
                int kk = (idx & 7) << 2;
                wa[q] = *(const float4*)(wx + (size_t)r * DD + (k0 + 32) + kk);
            }
        }

        #pragma unroll
        for (int kk = 0; kk < 32; ++kk) {
            ull a01 = *(const ull*)&xs_t[kk][trow4];
            ull a23 = *(const ull*)&xs_t[kk][trow4 + 2];
            float b0 = ws[kk][tcol];
            float b1 = ws[kk][tcol + 32];
            float b2 = ws[kk][tcol + 64];
            ull b0p = f2p(b0, b0);
            ull b1p = f2p(b1, b1);
            ull b2p = f2p(b2, b2);
            acc2[0][0] = fma2p(a01, b0p, acc2[0][0]);
            acc2[0][1] = fma2p(a01, b1p, acc2[0][1]);
            acc2[0][2] = fma2p(a01, b2p, acc2[0][2]);
            acc2[1][0] = fma2p(a23, b0p, acc2[1][0]);
            acc2[1][1] = fma2p(a23, b1p, acc2[1][1]);
            acc2[1][2] = fma2p(a23, b2p, acc2[1][2]);
        }
        __syncthreads();
    }

    #pragma unroll
    for (int p = 0; p < 2; ++p) {
        #pragma unroll
        for (int j = 0; j < 3; ++j) {
            float lo, hi;
            p2f(acc2[p][j], lo, hi);
            g_xp[(size_t)(row0 + trow4 + 2 * p) * NE + tcol + 32 * j] = lo;
            g_xp[(size_t)(row0 + trow4 + 2 * p + 1) * NE + tcol + 32 * j] = hi;
        }
    }
}

// ---------------------------------------------------------------------------
// GEMM2: delta[row, d] = softplus( sum_r dr[row, r] * Wdt[d, r] + bias[d] )
// (M=4096, N=1024, K=64). Tile 64x64, 256 threads, micro 8x2, f32x2 packed.
// ---------------------------------------------------------------------------
__global__ void __launch_bounds__(256) k_gemm2(const float* __restrict__ wdt,
                                               const float* __restrict__ bias) {
    __shared__ float ds_t[64][66];   // [k][row], 264B rows (8B multiple)
    __shared__ float ws2[64][64];    // [k][col]
    const int t = threadIdx.x;
    const int row0 = blockIdx.y * 64;
    const int col0 = blockIdx.x * 64;

    #pragma unroll
    for (int q = 0; q < 4; ++q) {
        int idx = t + q * 256;
        int r = idx >> 4;
        int kk = (idx & 15) << 2;
        float4 v = *(const float4*)(g_xp + (size_t)(row0 + r) * NE + kk);
        ds_t[kk + 0][r] = v.x;
        ds_t[kk + 1][r] = v.y;
        ds_t[kk + 2][r] = v.z;
        ds_t[kk + 3][r] = v.w;
    }
    #pragma unroll
    for (int q = 0; q < 4; ++q) {
        int idx = t + q * 256;
        int r = idx >> 4;               // col index 0..63
        int kk = (idx & 15) << 2;
        float4 v = *(const float4*)(wdt + (size_t)(col0 + r) * RK + kk);
        ws2[kk][r] = v.x; ws2[kk + 1][r] = v.y; ws2[kk + 2][r] = v.z; ws2[kk + 3][r] = v.w;
    }
    __syncthreads();

    const int trow8 = (t >> 5) * 8;
    const int tcol = t & 31;

    ull acc2[4][2] = {};
    #pragma unroll
    for (int kk = 0; kk < 64; ++kk) {
        float b0 = ws2[kk][tcol];
        float b1 = ws2[kk][tcol + 32];
        ull b0p = f2p(b0, b0);
        ull b1p = f2p(b1, b1);
        #pragma unroll
        for (int p = 0; p < 4; ++p) {
            ull a = *(const ull*)&ds_t[kk][trow8 + 2 * p];
            acc2[p][0] = fma2p(a, b0p, acc2[p][0]);
            acc2[p][1] = fma2p(a, b1p, acc2[p][1]);
        }
    }

    #pragma unroll
    for (int p = 0; p < 4; ++p) {
        #pragma unroll
        for (int j = 0; j < 2; ++j) {
            float lo, hi;
            p2f(acc2[p][j], lo, hi);
            int col = col0 + tcol + 32 * j;
            float bcol = bias[col];
            #pragma unroll
            for (int hh = 0; hh < 2; ++hh) {
                int row = row0 + trow8 + 2 * p + hh;
                float z = (hh == 0 ? lo : hi) + bcol;
                // softplus(z) = max(z,0) + ln(1 + exp(-|z|))
                float az = fabsf(z);
                float e = ex2f_fast(-1.4426950408889634f * az);
                float l = lg2f_fast(1.0f + e) * 0.69314718055994531f;
                g_delta[(size_t)row * DD + col] = fmaxf(z, 0.0f) + l;
            }
        }
    }
}

// ---------------------------------------------------------------------------
// Scan pass 1: per (b, d, chunk) thread; packed-pair h update.
// prod(dA[n]) == exp2(A2[n] * sum(delta))
// ---------------------------------------------------------------------------
__global__ void __launch_bounds__(128) k_scan1(const float* __restrict__ x,
                                               const float* __restrict__ A_log) {
    const int d = blockIdx.x * 128 + threadIdx.x;
    const int c = blockIdx.y;
    const int b = blockIdx.z;

    const float l2e = 1.4426950408889634f;
    ull A2p[8];
    #pragma unroll
    for (int q = 0; q < 4; ++q) {
        float4 v = *(const float4*)(A_log + (size_t)d * NS + q * 4);
        A2p[q * 2 + 0] = f2p(-__expf(v.x) * l2e, -__expf(v.y) * l2e);
        A2p[q * 2 + 1] = f2p(-__expf(v.z) * l2e, -__expf(v.w) * l2e);
    }

    ull h2[8] = {};
    float sdl = 0.0f;

    const int rbase = b * LL + c * LC;
    #pragma unroll 4
    for (int s = 0; s < LC; ++s) {
        const int row = rbase + s;
        const float dl = g_delta[(size_t)row * DD + d];
        const float xv = x[(size_t)row * DD + d];
        sdl += dl;
        const float dx = dl * xv;
        const ull dlp = f2p(dl, dl);
        const ull dxp = f2p(dx, dx);
        const ulonglong2* Bp = (const ulonglong2*)(g_xp + (size_t)row * NE + RK);
        ulonglong2 Bv[4];
        #pragma unroll
        for (int u = 0; u < 4; ++u) Bv[u] = Bp[u];
        #pragma unroll
        for (int q = 0; q < 8; ++q) {
            ull arg = mul2p(dlp, A2p[q]);
            float alo, ahi;
            p2f(arg, alo, ahi);
            ull a2 = f2p(ex2f_fast(alo), ex2f_fast(ahi));
            ull Bq = (q & 1) ? Bv[q >> 1].y : Bv[q >> 1].x;
            h2[q] = fma2p(a2, h2[q], mul2p(dxp, Bq));
        }
    }

    const size_t off = ((size_t)(b * NC + c) * DD + d) * NS;
    const ull sdlp = f2p(sdl, sdl);
    #pragma unroll
    for (int u = 0; u < 4; ++u) {
        ulonglong2 st;
        st.x = h2[2 * u]; st.y = h2[2 * u + 1];
        *(ulonglong2*)(g_ho + off + u * 4) = st;

        ull a0 = mul2p(sdlp, A2p[2 * u]);
        ull a1 = mul2p(sdlp, A2p[2 * u + 1]);
        float x0, x1, x2, x3;
        p2f(a0, x0, x1);
        p2f(a1, x2, x3);
        ulonglong2 ap;
        ap.x = f2p(ex2f_fast(x0), ex2f_fast(x1));
        ap.y = f2p(ex2f_fast(x2), ex2f_fast(x3));
        *(ulonglong2*)(g_ap + off + u * 4) = ap;
    }
}

// ---------------------------------------------------------------------------
// Combine: sequential over chunks per (b,d,n) thread, batched loads for MLP.
// ---------------------------------------------------------------------------
__global__ void __launch_bounds__(128) k_comb() {
    const int gid = blockIdx.x * 128 + threadIdx.x;     // 0 .. BB*DDNS-1
    const int b = gid >> 14;            // DDNS = 16384
    const int rem = gid & (DDNS - 1);   // d*NS + n
    float h = 0.0f;
    #pragma unroll
    for (int c0 = 0; c0 < NC; c0 += 16) {
        float av[16], hv[16];
        #pragma unroll
        for (int j = 0; j < 16; ++j) {
            const size_t off = (size_t)(b * NC + c0 + j) * DDNS + rem;
            av[j] = g_ap[off];
            hv[j] = g_ho[off];
        }
        #pragma unroll
        for (int j = 0; j < 16; ++j) {
            const size_t off = (size_t)(b * NC + c0 + j) * DDNS + rem;
            g_hi[off] = h;
            h = fmaf(av[j], h, hv[j]);
        }
    }
}

// ---------------------------------------------------------------------------
// Scan pass 2: replay with h_in, emit y = sum_n h[n]*C[n] + x*D (packed pairs)
// ---------------------------------------------------------------------------
__global__ void __launch_bounds__(128) k_scan2(const float* __restrict__ x,
                                               const float* __restrict__ A_log,
                                               const float* __restrict__ Dw,
                                               float* __restrict__ out) {
    const int d = blockIdx.x * 128 + threadIdx.x;
    const int c = blockIdx.y;
    const int b = blockIdx.z;

    const float l2e = 1.4426950408889634f;
    ull A2p[8];
    #pragma unroll
    for (int q = 0; q < 4; ++q) {
        float4 v = *(const float4*)(A_log + (size_t)d * NS + q * 4);
        A2p[q * 2 + 0] = f2p(-__expf(v.x) * l2e, -__expf(v.y) * l2e);
        A2p[q * 2 + 1] = f2p(-__expf(v.z) * l2e, -__expf(v.w) * l2e);
    }
    const float Dv = Dw[d];

    ull h2[8];
    {
        const size_t off = ((size_t)(b * NC + c) * DD + d) * NS;
        #pragma unroll
        for (int u = 0; u < 4; ++u) {
            ulonglong2 v = *(const ulonglong2*)(g_hi + off + u * 4);
            h2[2 * u] = v.x;
            h2[2 * u + 1] = v.y;
        }
    }

    const int rbase = b * LL + c * LC;
    #pragma unroll 2
    for (int s = 0; s < LC; ++s) {
        const int row = rbase + s;
        const float dl = g_delta[(size_t)row * DD + d];
        const float xv = x[(size_t)row * DD + d];
        const float dx = dl * xv;
        const ull dlp = f2p(dl, dl);
        const ull dxp = f2p(dx, dx);
        const ulonglong2* Bp = (const ulonglong2*)(g_xp + (size_t)row * NE + RK);
        ulonglong2 BCv[8];   // 4 for B (n 0..15), 4 for C
        #pragma unroll
        for (int u = 0; u < 8; ++u) BCv[u] = Bp[u];

        ull y2 = 0;
        #pragma unroll
        for (int q = 0; q < 8; ++q) {
            ull arg = mul2p(dlp, A2p[q]);
            float alo, ahi;
            p2f(arg, alo, ahi);
            ull a2 = f2p(ex2f_fast(alo), ex2f_fast(ahi));
            ull Bq = (q & 1) ? BCv[q >> 1].y : BCv[q >> 1].x;
            ull Cq = (q & 1) ? BCv[4 + (q >> 1)].y : BCv[4 + (q >> 1)].x;
            h2[q] = fma2p(a2, h2[q], mul2p(dxp, Bq));
            y2 = fma2p(h2[q], Cq, y2);
        }
        float ylo, yhi;
        p2f(y2, ylo, yhi);
        out[(size_t)row * DD + d] = fmaf(xv, Dv, ylo + yhi);
    }
}

// ---------------------------------------------------------------------------
extern "C" void kernel_launch(void* const* d_in, const int* in_sizes, int n_in,
                              void* d_out, int out_size) {
    const float* x     = (const float*)d_in[0];
    const float* A_log = (const float*)d_in[1];
    const float* Dw    = (const float*)d_in[2];
    const float* wx    = (const float*)d_in[3];
    const float* wdt   = (const float*)d_in[4];
    const float* bias  = (const float*)d_in[5];
    float* out = (float*)d_out;

    k_gemm1<<<NROW / 32, 256>>>(x, wx);

    dim3 g2(DD / 64, NROW / 64);
    k_gemm2<<<g2, 256>>>(wdt, bias);

    dim3 gs(DD / 128, NC, BB);
    k_scan1<<<gs, 128>>>(x, A_log);

    k_comb<<<(BB * DDNS) / 128, 128>>>();

    k_scan2<<<gs, 128>>>(x, A_log, Dw, out);
}

// round 4
// speedup vs baseline: 1.2534x; 1.0708x over previous
#include <cuda_runtime.h>
#include <math.h>

// Problem constants
#define BB 2
#define LL 2048
#define DD 1024
#define NS 16        // D_STATE
#define RK 64        // DT_RANK
#define NE 96        // RK + 2*NS
#define NROW (BB*LL) // 4096
#define NC 64        // chunks per sequence
#define LC (LL/NC)   // 32 steps per chunk
#define DDNS (DD*NS) // 16384

typedef unsigned long long ull;

// Scratch (device globals; no allocations allowed)
__device__ float g_xp0[NROW * NE];       // K-split partial 0
__device__ float g_xp1[NROW * NE];       // K-split partial 1
__device__ float g_delta[NROW * DD];     // [row][d]
__device__ float g_ap[BB * NC * DDNS];
__device__ float g_ho[BB * NC * DDNS];
__device__ float g_hi[BB * NC * DDNS];

__device__ __forceinline__ float ex2f_fast(float x) {
    float r;
    asm("ex2.approx.f32 %0, %1;" : "=f"(r) : "f"(x));
    return r;
}
__device__ __forceinline__ float lg2f_fast(float x) {
    float r;
    asm("lg2.approx.f32 %0, %1;" : "=f"(r) : "f"(x));
    return r;
}
// packed fp32 helpers (Blackwell f32x2 pipe)
__device__ __forceinline__ ull f2p(float lo, float hi) {
    ull r;
    asm("mov.b64 %0, {%1, %2};" : "=l"(r) : "f"(lo), "f"(hi));
    return r;
}
__device__ __forceinline__ void p2f(ull p, float& lo, float& hi) {
    asm("mov.b64 {%0, %1}, %2;" : "=f"(lo), "=f"(hi) : "l"(p));
}
__device__ __forceinline__ ull fma2p(ull a, ull b, ull c) {
    ull d;
    asm("fma.rn.f32x2 %0, %1, %2, %3;" : "=l"(d) : "l"(a), "l"(b), "l"(c));
    return d;
}
__device__ __forceinline__ ull mul2p(ull a, ull b) {
    ull d;
    asm("mul.rn.f32x2 %0, %1, %2;" : "=l"(d) : "l"(a), "l"(b));
    return d;
}

// ---------------------------------------------------------------------------
// GEMM1: xp[row, e] = sum_k x[row, k] * Wx[e, k]    (M=4096, N=96, K=1024)
// K-split 2: blockIdx.y selects K half and output partial buffer.
// Tile 32 rows x 96 cols, BK=32, 256 threads, micro 4x3, f32x2-packed rows.
// ---------------------------------------------------------------------------
__global__ void __launch_bounds__(256) k_gemm1(const float* __restrict__ x,
                                               const float* __restrict__ wx) {
    __shared__ float xs_t[32][36];   // [k][row]
    __shared__ float ws[32][100];    // [k][col]

    const int t = threadIdx.x;
    const int row0 = blockIdx.x * 32;
    const int kbase = blockIdx.y * 512;
    const int trow4 = (t >> 5) * 4;
    const int tcol = t & 31;

    const int xr = t >> 3;            // 0..31
    const int xk = (t & 7) << 2;      // 0,4,..,28

    float4 xa;
    float4 wa[3];
    xa = *(const float4*)(x + (size_t)(row0 + xr) * DD + kbase + xk);
    #pragma unroll
    for (int q = 0; q < 3; ++q) {
        int idx = t + q * 256;
        int r = idx >> 3;
        int kk = (idx & 7) << 2;
        wa[q] = *(const float4*)(wx + (size_t)r * DD + kbase + kk);
    }

    ull acc2[2][3] = {};

    for (int k0 = 0; k0 < 512; k0 += 32) {
        xs_t[xk + 0][xr] = xa.x;
        xs_t[xk + 1][xr] = xa.y;
        xs_t[xk + 2][xr] = xa.z;
        xs_t[xk + 3][xr] = xa.w;
        #pragma unroll
        for (int q = 0; q < 3; ++q) {
            int idx = t + q * 256;
            int r = idx >> 3;
            int kk = (idx & 7) << 2;
            ws[kk + 0][r] = wa[q].x;
            ws[kk + 1][r] = wa[q].y;
            ws[kk + 2][r] = wa[q].z;
            ws[kk + 3][r] = wa[q].w;
        }
        __syncthreads();

        if (k0 + 32 < 512) {
            xa = *(const float4*)(x + (size_t)(row0 + xr) * DD + kbase + (k0 + 32) + xk);
            #pragma unroll
            for (int q = 0; q < 3; ++q) {
                int idx = t + q * 256;
                int r = idx >> 3;
                int kk = (idx & 7) << 2;
                wa[q] = *(const float4*)(wx + (size_t)r * DD + kbase + (k0 + 32) + kk);
            }
        }

        #pragma unroll
        for (int kk = 0; kk < 32; ++kk) {
            ull a01 = *(const ull*)&xs_t[kk][trow4];
            ull a23 = *(const ull*)&xs_t[kk][trow4 + 2];
            float b0 = ws[kk][tcol];
            float b1 = ws[kk][tcol + 32];
            float b2 = ws[kk][tcol + 64];
            ull b0p = f2p(b0, b0);
            ull b1p = f2p(b1, b1);
            ull b2p = f2p(b2, b2);
            acc2[0][0] = fma2p(a01, b0p, acc2[0][0]);
            acc2[0][1] = fma2p(a01, b1p, acc2[0][1]);
            acc2[0][2] = fma2p(a01, b2p, acc2[0][2]);
            acc2[1][0] = fma2p(a23, b0p, acc2[1][0]);
            acc2[1][1] = fma2p(a23, b1p, acc2[1][1]);
            acc2[1][2] = fma2p(a23, b2p, acc2[1][2]);
        }
        __syncthreads();
    }

    float* dst = blockIdx.y ? g_xp1 : g_xp0;
    #pragma unroll
    for (int p = 0; p < 2; ++p) {
        #pragma unroll
        for (int j = 0; j < 3; ++j) {
            float lo, hi;
            p2f(acc2[p][j], lo, hi);
            dst[(size_t)(row0 + trow4 + 2 * p) * NE + tcol + 32 * j] = lo;
            dst[(size_t)(row0 + trow4 + 2 * p + 1) * NE + tcol + 32 * j] = hi;
        }
    }
}

// ---------------------------------------------------------------------------
// GEMM2: delta[row, d] = softplus( sum_r dr[row, r] * Wdt[d, r] + bias[d] )
// dr = g_xp0 + g_xp1 (K-split partials). Tile 64x64, micro 8x2, f32x2 packed.
// ---------------------------------------------------------------------------
__global__ void __launch_bounds__(256) k_gemm2(const float* __restrict__ wdt,
                                               const float* __restrict__ bias) {
    __shared__ float ds_t[64][66];   // [k][row]
    __shared__ float ws2[64][64];    // [k][col]
    const int t = threadIdx.x;
    const int row0 = blockIdx.y * 64;
    const int col0 = blockIdx.x * 64;

    #pragma unroll
    for (int q = 0; q < 4; ++q) {
        int idx = t + q * 256;
        int r = idx >> 4;
        int kk = (idx & 15) << 2;
        float4 v0 = *(const float4*)(g_xp0 + (size_t)(row0 + r) * NE + kk);
        float4 v1 = *(const float4*)(g_xp1 + (size_t)(row0 + r) * NE + kk);
        ds_t[kk + 0][r] = v0.x + v1.x;
        ds_t[kk + 1][r] = v0.y + v1.y;
        ds_t[kk + 2][r] = v0.z + v1.z;
        ds_t[kk + 3][r] = v0.w + v1.w;
    }
    #pragma unroll
    for (int q = 0; q < 4; ++q) {
        int idx = t + q * 256;
        int r = idx >> 4;               // col index 0..63
        int kk = (idx & 15) << 2;
        float4 v = *(const float4*)(wdt + (size_t)(col0 + r) * RK + kk);
        ws2[kk][r] = v.x; ws2[kk + 1][r] = v.y; ws2[kk + 2][r] = v.z; ws2[kk + 3][r] = v.w;
    }
    __syncthreads();

    const int trow8 = (t >> 5) * 8;
    const int tcol = t & 31;

    ull acc2[4][2] = {};
    #pragma unroll
    for (int kk = 0; kk < 64; ++kk) {
        float b0 = ws2[kk][tcol];
        float b1 = ws2[kk][tcol + 32];
        ull b0p = f2p(b0, b0);
        ull b1p = f2p(b1, b1);
        #pragma unroll
        for (int p = 0; p < 4; ++p) {
            ull a = *(const ull*)&ds_t[kk][trow8 + 2 * p];
            acc2[p][0] = fma2p(a, b0p, acc2[p][0]);
            acc2[p][1] = fma2p(a, b1p, acc2[p][1]);
        }
    }

    #pragma unroll
    for (int p = 0; p < 4; ++p) {
        #pragma unroll
        for (int j = 0; j < 2; ++j) {
            float lo, hi;
            p2f(acc2[p][j], lo, hi);
            int col = col0 + tcol + 32 * j;
            float bcol = bias[col];
            #pragma unroll
            for (int hh = 0; hh < 2; ++hh) {
                int row = row0 + trow8 + 2 * p + hh;
                float z = (hh == 0 ? lo : hi) + bcol;
                float az = fabsf(z);
                float e = ex2f_fast(-1.4426950408889634f * az);
                float l = lg2f_fast(1.0f + e) * 0.69314718055994531f;
                g_delta[(size_t)row * DD + col] = fmaxf(z, 0.0f) + l;
            }
        }
    }
}

// ---------------------------------------------------------------------------
// Scan pass 1: per (b, d, chunk) thread; B staged in smem (block-shared rows).
// ---------------------------------------------------------------------------
__global__ void __launch_bounds__(128) k_scan1(const float* __restrict__ x,
                                               const float* __restrict__ A_log) {
    __shared__ float s_b[LC][16];
    const int t = threadIdx.x;
    const int d = blockIdx.x * 128 + t;
    const int c = blockIdx.y;
    const int b = blockIdx.z;
    const int rbase = b * LL + c * LC;

    // cooperative stage of B rows (sum of K-split partials)
    {
        int row = t >> 2;           // 0..31
        int c4 = (t & 3) << 2;      // 0,4,8,12
        float4 v0 = *(const float4*)(g_xp0 + (size_t)(rbase + row) * NE + RK + c4);
        float4 v1 = *(const float4*)(g_xp1 + (size_t)(rbase + row) * NE + RK + c4);
        float4 s; s.x = v0.x + v1.x; s.y = v0.y + v1.y; s.z = v0.z + v1.z; s.w = v0.w + v1.w;
        *(float4*)&s_b[row][c4] = s;
    }

    const float l2e = 1.4426950408889634f;
    ull A2p[8];
    #pragma unroll
    for (int q = 0; q < 4; ++q) {
        float4 v = *(const float4*)(A_log + (size_t)d * NS + q * 4);
        A2p[q * 2 + 0] = f2p(-__expf(v.x) * l2e, -__expf(v.y) * l2e);
        A2p[q * 2 + 1] = f2p(-__expf(v.z) * l2e, -__expf(v.w) * l2e);
    }
    __syncthreads();

    ull h2[8] = {};
    float sdl = 0.0f;

    #pragma unroll 4
    for (int s = 0; s < LC; ++s) {
        const int row = rbase + s;
        const float dl = g_delta[(size_t)row * DD + d];
        const float xv = x[(size_t)row * DD + d];
        sdl += dl;
        const float dx = dl * xv;
        const ull dlp = f2p(dl, dl);
        const ull dxp = f2p(dx, dx);
        #pragma unroll
        for (int q = 0; q < 8; ++q) {
            ull arg = mul2p(dlp, A2p[q]);
            float alo, ahi;
            p2f(arg, alo, ahi);
            ull a2 = f2p(ex2f_fast(alo), ex2f_fast(ahi));
            ull Bq = *(const ull*)&s_b[s][2 * q];
            h2[q] = fma2p(a2, h2[q], mul2p(dxp, Bq));
        }
    }

    const size_t off = ((size_t)(b * NC + c) * DD + d) * NS;
    const ull sdlp = f2p(sdl, sdl);
    #pragma unroll
    for (int u = 0; u < 4; ++u) {
        ulonglong2 st;
        st.x = h2[2 * u]; st.y = h2[2 * u + 1];
        *(ulonglong2*)(g_ho + off + u * 4) = st;

        ull a0 = mul2p(sdlp, A2p[2 * u]);
        ull a1 = mul2p(sdlp, A2p[2 * u + 1]);
        float x0, x1, x2, x3;
        p2f(a0, x0, x1);
        p2f(a1, x2, x3);
        ulonglong2 ap;
        ap.x = f2p(ex2f_fast(x0), ex2f_fast(x1));
        ap.y = f2p(ex2f_fast(x2), ex2f_fast(x3));
        *(ulonglong2*)(g_ap + off + u * 4) = ap;
    }
}

// ---------------------------------------------------------------------------
// Combine: sequential over chunks per (b,d,n) thread, batched loads for MLP.
// ---------------------------------------------------------------------------
__global__ void __launch_bounds__(128) k_comb() {
    const int gid = blockIdx.x * 128 + threadIdx.x;     // 0 .. BB*DDNS-1
    const int b = gid >> 14;            // DDNS = 16384
    const int rem = gid & (DDNS - 1);   // d*NS + n
    float h = 0.0f;
    #pragma unroll
    for (int c0 = 0; c0 < NC; c0 += 16) {
        float av[16], hv[16];
        #pragma unroll
        for (int j = 0; j < 16; ++j) {
            const size_t off = (size_t)(b * NC + c0 + j) * DDNS + rem;
            av[j] = g_ap[off];
            hv[j] = g_ho[off];
        }
        #pragma unroll
        for (int j = 0; j < 16; ++j) {
            const size_t off = (size_t)(b * NC + c0 + j) * DDNS + rem;
            g_hi[off] = h;
            h = fmaf(av[j], h, hv[j]);
        }
    }
}

// ---------------------------------------------------------------------------
// Scan pass 2: replay with h_in; B and C staged in smem; y output.
// ---------------------------------------------------------------------------
__global__ void __launch_bounds__(128) k_scan2(const float* __restrict__ x,
                                               const float* __restrict__ A_log,
                                               const float* __restrict__ Dw,
                                               float* __restrict__ out) {
    __shared__ float s_bc[LC][32];   // [step][0..15 = B, 16..31 = C]
    const int t = threadIdx.x;
    const int d = blockIdx.x * 128 + t;
    const int c = blockIdx.y;
    const int b = blockIdx.z;
    const int rbase = b * LL + c * LC;

    // cooperative stage of B|C rows (sum of K-split partials)
    {
        int row = t >> 2;           // 0..31
        int c4 = (t & 3) << 2;      // 0,4,8,12
        float4 v0 = *(const float4*)(g_xp0 + (size_t)(rbase + row) * NE + RK + c4);
        float4 v1 = *(const float4*)(g_xp1 + (size_t)(rbase + row) * NE + RK + c4);
        float4 s0; s0.x = v0.x + v1.x; s0.y = v0.y + v1.y; s0.z = v0.z + v1.z; s0.w = v0.w + v1.w;
        *(float4*)&s_bc[row][c4] = s0;
        float4 w0 = *(const float4*)(g_xp0 + (size_t)(rbase + row) * NE + RK + NS + c4);
        float4 w1 = *(const float4*)(g_xp1 + (size_t)(rbase + row) * NE + RK + NS + c4);
        float4 s1; s1.x = w0.x + w1.x; s1.y = w0.y + w1.y; s1.z = w0.z + w1.z; s1.w = w0.w + w1.w;
        *(float4*)&s_bc[row][16 + c4] = s1;
    }

    const float l2e = 1.4426950408889634f;
    ull A2p[8];
    #pragma unroll
    for (int q = 0; q < 4; ++q) {
        float4 v = *(const float4*)(A_log + (size_t)d * NS + q * 4);
        A2p[q * 2 + 0] = f2p(-__expf(v.x) * l2e, -__expf(v.y) * l2e);
        A2p[q * 2 + 1] = f2p(-__expf(v.z) * l2e, -__expf(v.w) * l2e);
    }
    const float Dv = Dw[d];

    ull h2[8];
    {
        const size_t off = ((size_t)(b * NC + c) * DD + d) * NS;
        #pragma unroll
        for (int u = 0; u < 4; ++u) {
            ulonglong2 v = *(const ulonglong2*)(g_hi + off + u * 4);
            h2[2 * u] = v.x;
            h2[2 * u + 1] = v.y;
        }
    }
    __syncthreads();

    #pragma unroll 4
    for (int s = 0; s < LC; ++s) {
        const int row = rbase + s;
        const float dl = g_delta[(size_t)row * DD + d];
        const float xv = x[(size_t)row * DD + d];
        const float dx = dl * xv;
        const ull dlp = f2p(dl, dl);
        const ull dxp = f2p(dx, dx);

        ull y2 = 0;
        #pragma unroll
        for (int q = 0; q < 8; ++q) {
            ull arg = mul2p(dlp, A2p[q]);
            float alo, ahi;
            p2f(arg, alo, ahi);
            ull a2 = f2p(ex2f_fast(alo), ex2f_fast(ahi));
            ull Bq = *(const ull*)&s_bc[s][2 * q];
            ull Cq = *(const ull*)&s_bc[s][16 + 2 * q];
            h2[q] = fma2p(a2, h2[q], mul2p(dxp, Bq));
            y2 = fma2p(h2[q], Cq, y2);
        }
        float ylo, yhi;
        p2f(y2, ylo, yhi);
        out[(size_t)row * DD + d] = fmaf(xv, Dv, ylo + yhi);
    }
}

// ---------------------------------------------------------------------------
extern "C" void kernel_launch(void* const* d_in, const int* in_sizes, int n_in,
                              void* d_out, int out_size) {
    const float* x     = (const float*)d_in[0];
    const float* A_log = (const float*)d_in[1];
    const float* Dw    = (const float*)d_in[2];
    const float* wx    = (const float*)d_in[3];
    const float* wdt   = (const float*)d_in[4];
    const float* bias  = (const float*)d_in[5];
    float* out = (float*)d_out;

    dim3 g1(NROW / 32, 2);
    k_gemm1<<<g1, 256>>>(x, wx);

    dim3 g2(DD / 64, NROW / 64);
    k_gemm2<<<g2, 256>>>(wdt, bias);

    dim3 gs(DD / 128, NC, BB);
    k_scan1<<<gs, 128>>>(x, A_log);

    k_comb<<<(BB * DDNS) / 128, 128>>>();

    k_scan2<<<gs, 128>>>(x, A_log, Dw, out);
}

// round 5
// speedup vs baseline: 1.3212x; 1.0541x over previous
#include <cuda_runtime.h>
#include <math.h>

// Problem constants
#define BB 2
#define LL 2048
#define DD 1024
#define NS 16        // D_STATE
#define RK 64        // DT_RANK
#define NE 96        // RK + 2*NS
#define NROW (BB*LL) // 4096
#define NC 64        // chunks per sequence
#define LC (LL/NC)   // 32 steps per chunk
#define DDNS (DD*NS) // 16384
#define SC 8         // superchunks
#define CPS (NC/SC)  // chunks per superchunk = 8

typedef unsigned long long ull;

// Scratch (device globals; no allocations allowed)
__device__ float g_xp0[NROW * NE];       // K-split partial 0
__device__ float g_xp1[NROW * NE];       // K-split partial 1
__device__ float g_delta[NROW * DD];     // [row][d]
__device__ float g_ap[BB * NC * DDNS];
__device__ float g_ho[BB * NC * DDNS];
__device__ float g_hi[BB * NC * DDNS];
__device__ float g_sap[BB * SC * DDNS];
__device__ float g_sho[BB * SC * DDNS];
__device__ float g_shi[BB * SC * DDNS];

__device__ __forceinline__ float ex2f_fast(float x) {
    float r;
    asm("ex2.approx.f32 %0, %1;" : "=f"(r) : "f"(x));
    return r;
}
__device__ __forceinline__ float lg2f_fast(float x) {
    float r;
    asm("lg2.approx.f32 %0, %1;" : "=f"(r) : "f"(x));
    return r;
}
// packed fp32 helpers (Blackwell f32x2 pipe)
__device__ __forceinline__ ull f2p(float lo, float hi) {
    ull r;
    asm("mov.b64 %0, {%1, %2};" : "=l"(r) : "f"(lo), "f"(hi));
    return r;
}
__device__ __forceinline__ void p2f(ull p, float& lo, float& hi) {
    asm("mov.b64 {%0, %1}, %2;" : "=f"(lo), "=f"(hi) : "l"(p));
}
__device__ __forceinline__ ull fma2p(ull a, ull b, ull c) {
    ull d;
    asm("fma.rn.f32x2 %0, %1, %2, %3;" : "=l"(d) : "l"(a), "l"(b), "l"(c));
    return d;
}
__device__ __forceinline__ ull mul2p(ull a, ull b) {
    ull d;
    asm("mul.rn.f32x2 %0, %1, %2;" : "=l"(d) : "l"(a), "l"(b));
    return d;
}

// ---------------------------------------------------------------------------
// GEMM1: xp[row, e] = sum_k x[row, k] * Wx[e, k]    (M=4096, N=96, K=1024)
// K-split 2. Tile 64 rows x 96 cols, BK=32, 256 threads, micro 8x3 (4 ull x 3).
// a-rows read as 2x broadcast LDS.128; b scalar; f32x2-packed accumulators.
// ---------------------------------------------------------------------------
__global__ void __launch_bounds__(256) k_gemm1(const float* __restrict__ x,
                                               const float* __restrict__ wx) {
    __shared__ float xs_t[32][68];   // [k][row], 272B rows (16B aligned)
    __shared__ float ws[32][100];    // [k][col]

    const int t = threadIdx.x;
    const int row0 = blockIdx.x * 64;
    const int kbase = blockIdx.y * 512;
    const int trow8 = (t >> 5) * 8;  // warp-uniform row group (8 rows/warp)
    const int tcol = t & 31;

    // x loads: 2 float4 per thread (64 rows x 32 k = 512 float4)
    const int xr0 = t >> 3;                 // 0..31
    const int xr1 = 32 + (t >> 3);          // 32..63
    const int xk = (t & 7) << 2;            // 0,4,..,28

    float4 xa0, xa1;
    float4 wa[3];
    xa0 = *(const float4*)(x + (size_t)(row0 + xr0) * DD + kbase + xk);
    xa1 = *(const float4*)(x + (size_t)(row0 + xr1) * DD + kbase + xk);
    #pragma unroll
    for (int q = 0; q < 3; ++q) {
        int idx = t + q * 256;
        int r = idx >> 3;
        int kk = (idx & 7) << 2;
        wa[q] = *(const float4*)(wx + (size_t)r * DD + kbase + kk);
    }

    ull acc2[4][3] = {};

    for (int k0 = 0; k0 < 512; k0 += 32) {
        xs_t[xk + 0][xr0] = xa0.x;
        xs_t[xk + 1][xr0] = xa0.y;
        xs_t[xk + 2][xr0] = xa0.z;
        xs_t[xk + 3][xr0] = xa0.w;
        xs_t[xk + 0][xr1] = xa1.x;
        xs_t[xk + 1][xr1] = xa1.y;
        xs_t[xk + 2][xr1] = xa1.z;
        xs_t[xk + 3][xr1] = xa1.w;
        #pragma unroll
        for (int q = 0; q < 3; ++q) {
            int idx = t + q * 256;
            int r = idx >> 3;
            int kk = (idx & 7) << 2;
            ws[kk + 0][r] = wa[q].x;
            ws[kk + 1][r] = wa[q].y;
            ws[kk + 2][r] = wa[q].z;
            ws[kk + 3][r] = wa[q].w;
        }
        __syncthreads();

        if (k0 + 32 < 512) {
            xa0 = *(const float4*)(x + (size_t)(row0 + xr0) * DD + kbase + (k0 + 32) + xk);
            xa1 = *(const float4*)(x + (size_t)(row0 + xr1) * DD + kbase + (k0 + 32) + xk);
            #pragma unroll
            for (int q = 0; q < 3; ++q) {
                int idx = t + q * 256;
                int r = idx >> 3;
                int kk = (idx & 7) << 2;
                wa[q] = *(const float4*)(wx + (size_t)r * DD + kbase + (k0 + 32) + kk);
            }
        }

        #pragma unroll
        for (int kk = 0; kk < 32; ++kk) {
            ulonglong2 A0 = *(const ulonglong2*)&xs_t[kk][trow8];     // rows 0-3
            ulonglong2 A1 = *(const ulonglong2*)&xs_t[kk][trow8 + 4]; // rows 4-7
            float b0 = ws[kk][tcol];
            float b1 = ws[kk][tcol + 32];
            float b2 = ws[kk][tcol + 64];
            ull b0p = f2p(b0, b0);
            ull b1p = f2p(b1, b1);
            ull b2p = f2p(b2, b2);
            acc2[0][0] = fma2p(A0.x, b0p, acc2[0][0]);
            acc2[0][1] = fma2p(A0.x, b1p, acc2[0][1]);
            acc2[0][2] = fma2p(A0.x, b2p, acc2[0][2]);
            acc2[1][0] = fma2p(A0.y, b0p, acc2[1][0]);
            acc2[1][1] = fma2p(A0.y, b1p, acc2[1][1]);
            acc2[1][2] = fma2p(A0.y, b2p, acc2[1][2]);
            acc2[2][0] = fma2p(A1.x, b0p, acc2[2][0]);
            acc2[2][1] = fma2p(A1.x, b1p, acc2[2][1]);
            acc2[2][2] = fma2p(A1.x, b2p, acc2[2][2]);
            acc2[3][0] = fma2p(A1.y, b0p, acc2[3][0]);
            acc2[3][1] = fma2p(A1.y, b1p, acc2[3][1]);
            acc2[3][2] = fma2p(A1.y, b2p, acc2[3][2]);
        }
        __syncthreads();
    }

    float* dst = blockIdx.y ? g_xp1 : g_xp0;
    #pragma unroll
    for (int p = 0; p < 4; ++p) {
        #pragma unroll
        for (int j = 0; j < 3; ++j) {
            float lo, hi;
            p2f(acc2[p][j], lo, hi);
            dst[(size_t)(row0 + trow8 + 2 * p) * NE + tcol + 32 * j] = lo;
            dst[(size_t)(row0 + trow8 + 2 * p + 1) * NE + tcol + 32 * j] = hi;
        }
    }
}

// ---------------------------------------------------------------------------
// GEMM2: delta[row, d] = softplus( sum_r dr[row, r] * Wdt[d, r] + bias[d] )
// dr = g_xp0 + g_xp1 (K-split partials). Tile 64x64, micro 8x2, f32x2 packed.
// ---------------------------------------------------------------------------
__global__ void __launch_bounds__(256) k_gemm2(const float* __restrict__ wdt,
                                               const float* __restrict__ bias) {
    __shared__ float ds_t[64][66];   // [k][row]
    __shared__ float ws2[64][64];    // [k][col]
    const int t = threadIdx.x;
    const int row0 = blockIdx.y * 64;
    const int col0 = blockIdx.x * 64;

    #pragma unroll
    for (int q = 0; q < 4; ++q) {
        int idx = t + q * 256;
        int r = idx >> 4;
        int kk = (idx & 15) << 2;
        float4 v0 = *(const float4*)(g_xp0 + (size_t)(row0 + r) * NE + kk);
        float4 v1 = *(const float4*)(g_xp1 + (size_t)(row0 + r) * NE + kk);
        ds_t[kk + 0][r] = v0.x + v1.x;
        ds_t[kk + 1][r] = v0.y + v1.y;
        ds_t[kk + 2][r] = v0.z + v1.z;
        ds_t[kk + 3][r] = v0.w + v1.w;
    }
    #pragma unroll
    for (int q = 0; q < 4; ++q) {
        int idx = t + q * 256;
        int r = idx >> 4;               // col index 0..63
        int kk = (idx & 15) << 2;
        float4 v = *(const float4*)(wdt + (size_t)(col0 + r) * RK + kk);
        ws2[kk][r] = v.x; ws2[kk + 1][r] = v.y; ws2[kk + 2][r] = v.z; ws2[kk + 3][r] = v.w;
    }
    __syncthreads();

    const int trow8 = (t >> 5) * 8;
    const int tcol = t & 31;

    ull acc2[4][2] = {};
    #pragma unroll
    for (int kk = 0; kk < 64; ++kk) {
        float b0 = ws2[kk][tcol];
        float b1 = ws2[kk][tcol + 32];
        ull b0p = f2p(b0, b0);
        ull b1p = f2p(b1, b1);
        #pragma unroll
        for (int p = 0; p < 4; ++p) {
            ull a = *(const ull*)&ds_t[kk][trow8 + 2 * p];
            acc2[p][0] = fma2p(a, b0p, acc2[p][0]);
            acc2[p][1] = fma2p(a, b1p, acc2[p][1]);
        }
    }

    #pragma unroll
    for (int p = 0; p < 4; ++p) {
        #pragma unroll
        for (int j = 0; j < 2; ++j) {
            float lo, hi;
            p2f(acc2[p][j], lo, hi);
            int col = col0 + tcol + 32 * j;
            float bcol = bias[col];
            #pragma unroll
            for (int hh = 0; hh < 2; ++hh) {
                int row = row0 + trow8 + 2 * p + hh;
                float z = (hh == 0 ? lo : hi) + bcol;
                float az = fabsf(z);
                float e = ex2f_fast(-1.4426950408889634f * az);
                float l = lg2f_fast(1.0f + e) * 0.69314718055994531f;
                g_delta[(size_t)row * DD + col] = fmaxf(z, 0.0f) + l;
            }
        }
    }
}

// ---------------------------------------------------------------------------
// Scan pass 1: per (b, d, chunk) thread; B staged in smem; scalar MUFU args.
// ---------------------------------------------------------------------------
__global__ void __launch_bounds__(128) k_scan1(const float* __restrict__ x,
                                               const float* __restrict__ A_log) {
    __shared__ float s_b[LC][16];
    const int t = threadIdx.x;
    const int d = blockIdx.x * 128 + t;
    const int c = blockIdx.y;
    const int b = blockIdx.z;
    const int rbase = b * LL + c * LC;

    // cooperative stage of B rows (sum of K-split partials)
    {
        int row = t >> 2;           // 0..31
        int c4 = (t & 3) << 2;      // 0,4,8,12
        float4 v0 = *(const float4*)(g_xp0 + (size_t)(rbase + row) * NE + RK + c4);
        float4 v1 = *(const float4*)(g_xp1 + (size_t)(rbase + row) * NE + RK + c4);
        float4 s; s.x = v0.x + v1.x; s.y = v0.y + v1.y; s.z = v0.z + v1.z; s.w = v0.w + v1.w;
        *(float4*)&s_b[row][c4] = s;
    }

    const float l2e = 1.4426950408889634f;
    float A2[NS];
    #pragma unroll
    for (int q = 0; q < 4; ++q) {
        float4 v = *(const float4*)(A_log + (size_t)d * NS + q * 4);
        A2[q * 4 + 0] = -__expf(v.x) * l2e;
        A2[q * 4 + 1] = -__expf(v.y) * l2e;
        A2[q * 4 + 2] = -__expf(v.z) * l2e;
        A2[q * 4 + 3] = -__expf(v.w) * l2e;
    }
    __syncthreads();

    ull h2[8] = {};
    float sdl = 0.0f;

    const float* dptr = g_delta + (size_t)rbase * DD + d;
    const float* xptr = x + (size_t)rbase * DD + d;
    float dl = dptr[0];
    float xv = xptr[0];

    #pragma unroll 4
    for (int s = 0; s < LC; ++s) {
        float dln = 0.f, xvn = 0.f;
        if (s + 1 < LC) {
            dln = dptr[(size_t)(s + 1) * DD];
            xvn = xptr[(size_t)(s + 1) * DD];
        }
        sdl += dl;
        const float dx = dl * xv;
        const ull dxp = f2p(dx, dx);
        ulonglong2 Bq[4];
        #pragma unroll
        for (int u = 0; u < 4; ++u)
            Bq[u] = *(const ulonglong2*)&s_b[s][4 * u];
        #pragma unroll
        for (int q = 0; q < 8; ++q) {
            float e0 = ex2f_fast(dl * A2[2 * q]);
            float e1 = ex2f_fast(dl * A2[2 * q + 1]);
            ull a2 = f2p(e0, e1);
            ull Bv = (q & 1) ? Bq[q >> 1].y : Bq[q >> 1].x;
            h2[q] = fma2p(a2, h2[q], mul2p(dxp, Bv));
        }
        dl = dln; xv = xvn;
    }

    const size_t off = ((size_t)(b * NC + c) * DD + d) * NS;
    #pragma unroll
    for (int u = 0; u < 4; ++u) {
        ulonglong2 st;
        st.x = h2[2 * u]; st.y = h2[2 * u + 1];
        *(ulonglong2*)(g_ho + off + u * 4) = st;

        ulonglong2 ap;
        ap.x = f2p(ex2f_fast(A2[4 * u + 0] * sdl), ex2f_fast(A2[4 * u + 1] * sdl));
        ap.y = f2p(ex2f_fast(A2[4 * u + 2] * sdl), ex2f_fast(A2[4 * u + 3] * sdl));
        *(ulonglong2*)(g_ap + off + u * 4) = ap;
    }
}

// ---------------------------------------------------------------------------
// Combine level A: per (b, superchunk, rem) thread — aggregate 8 chunks.
// ---------------------------------------------------------------------------
__global__ void __launch_bounds__(256) k_combA() {
    const int gid = blockIdx.x * 256 + threadIdx.x;   // 0 .. BB*SC*DDNS-1
    const int b = gid >> 17;
    const int sc = (gid >> 14) & (SC - 1);
    const int rem = gid & (DDNS - 1);
    float av[CPS], hv[CPS];
    #pragma unroll
    for (int j = 0; j < CPS; ++j) {
        const size_t off = (size_t)(b * NC + sc * CPS + j) * DDNS + rem;
        av[j] = g_ap[off];
        hv[j] = g_ho[off];
    }
    float H = 0.0f, P = 1.0f;
    #pragma unroll
    for (int j = 0; j < CPS; ++j) {
        H = fmaf(av[j], H, hv[j]);
        P *= av[j];
    }
    const size_t soff = (size_t)(b * SC + sc) * DDNS + rem;
    g_sap[soff] = P;
    g_sho[soff] = H;
}

// ---------------------------------------------------------------------------
// Combine level B: per (b, rem) thread — scan across 8 superchunks.
// ---------------------------------------------------------------------------
__global__ void __launch_bounds__(256) k_combB() {
    const int gid = blockIdx.x * 256 + threadIdx.x;   // 0 .. BB*DDNS-1
    const int b = gid >> 14;
    const int rem = gid & (DDNS - 1);
    float av[SC], hv[SC];
    #pragma unroll
    for (int j = 0; j < SC; ++j) {
        const size_t off = (size_t)(b * SC + j) * DDNS + rem;
        av[j] = g_sap[off];
        hv[j] = g_sho[off];
    }
    float h = 0.0f;
    #pragma unroll
    for (int j = 0; j < SC; ++j) {
        const size_t off = (size_t)(b * SC + j) * DDNS + rem;
        g_shi[off] = h;
        h = fmaf(av[j], h, hv[j]);
    }
}

// ---------------------------------------------------------------------------
// Combine level C: per (b, superchunk, rem) thread — expand to per-chunk h_in.
// ---------------------------------------------------------------------------
__global__ void __launch_bounds__(256) k_combC() {
    const int gid = blockIdx.x * 256 + threadIdx.x;   // 0 .. BB*SC*DDNS-1
    const int b = gid >> 17;
    const int sc = (gid >> 14) & (SC - 1);
    const int rem = gid & (DDNS - 1);
    float av[CPS], hv[CPS];
    #pragma unroll
    for (int j = 0; j < CPS; ++j) {
        const size_t off = (size_t)(b * NC + sc * CPS + j) * DDNS + rem;
        av[j] = g_ap[off];
        hv[j] = g_ho[off];
    }
    float h = g_shi[(size_t)(b * SC + sc) * DDNS + rem];
    #pragma unroll
    for (int j = 0; j < CPS; ++j) {
        const size_t off = (size_t)(b * NC + sc * CPS + j) * DDNS + rem;
        g_hi[off] = h;
        h = fmaf(av[j], h, hv[j]);
    }
}

// ---------------------------------------------------------------------------
// Scan pass 2: replay with h_in; B and C staged in smem; y output.
// ---------------------------------------------------------------------------
__global__ void __launch_bounds__(128) k_scan2(const float* __restrict__ x,
                                               const float* __restrict__ A_log,
                                               const float* __restrict__ Dw,
                                               float* __restrict__ out) {
    __shared__ float s_bc[LC][32];   // [step][0..15 = B, 16..31 = C]
    const int t = threadIdx.x;
    const int d = blockIdx.x * 128 + t;
    const int c = blockIdx.y;
    const int b = blockIdx.z;
    const int rbase = b * LL + c * LC;

    // cooperative stage of B|C rows (sum of K-split partials)
    {
        int row = t >> 2;           // 0..31
        int c4 = (t & 3) << 2;      // 0,4,8,12
        float4 v0 = *(const float4*)(g_xp0 + (size_t)(rbase + row) * NE + RK + c4);
        float4 v1 = *(const float4*)(g_xp1 + (size_t)(rbase + row) * NE + RK + c4);
        float4 s0; s0.x = v0.x + v1.x; s0.y = v0.y + v1.y; s0.z = v0.z + v1.z; s0.w = v0.w + v1.w;
        *(float4*)&s_bc[row][c4] = s0;
        float4 w0 = *(const float4*)(g_xp0 + (size_t)(rbase + row) * NE + RK + NS + c4);
        float4 w1 = *(const float4*)(g_xp1 + (size_t)(rbase + row) * NE + RK + NS + c4);
        float4 s1; s1.x = w0.x + w1.x; s1.y = w0.y + w1.y; s1.z = w0.z + w1.z; s1.w = w0.w + w1.w;
        *(float4*)&s_bc[row][16 + c4] = s1;
    }

    const float l2e = 1.4426950408889634f;
    float A2[NS];
    #pragma unroll
    for (int q = 0; q < 4; ++q) {
        float4 v = *(const float4*)(A_log + (size_t)d * NS + q * 4);
        A2[q * 4 + 0] = -__expf(v.x) * l2e;
        A2[q * 4 + 1] = -__expf(v.y) * l2e;
        A2[q * 4 + 2] = -__expf(v.z) * l2e;
        A2[q * 4 + 3] = -__expf(v.w) * l2e;
    }
    const float Dv = Dw[d];

    ull h2[8];
    {
        const size_t off = ((size_t)(b * NC + c) * DD + d) * NS;
        #pragma unroll
        for (int u = 0; u < 4; ++u) {
            ulonglong2 v = *(const ulonglong2*)(g_hi + off + u * 4);
            h2[2 * u] = v.x;
            h2[2 * u + 1] = v.y;
        }
    }
    __syncthreads();

    const float* dptr = g_delta + (size_t)rbase * DD + d;
    const float* xptr = x + (size_t)rbase * DD + d;
    float dl = dptr[0];
    float xv = xptr[0];

    #pragma unroll 4
    for (int s = 0; s < LC; ++s) {
        float dln = 0.f, xvn = 0.f;
        if (s + 1 < LC) {
            dln = dptr[(size_t)(s + 1) * DD];
            xvn = xptr[(size_t)(s + 1) * DD];
        }
        const float dx = dl * xv;
        const ull dxp = f2p(dx, dx);
        ulonglong2 Bq[4], Cq[4];
        #pragma unroll
        for (int u = 0; u < 4; ++u) {
            Bq[u] = *(const ulonglong2*)&s_bc[s][4 * u];
            Cq[u] = *(const ulonglong2*)&s_bc[s][16 + 4 * u];
        }

        ull y2 = 0;
        #pragma unroll
        for (int q = 0; q < 8; ++q) {
            float e0 = ex2f_fast(dl * A2[2 * q]);
            float e1 = ex2f_fast(dl * A2[2 * q + 1]);
            ull a2 = f2p(e0, e1);
            ull Bv = (q & 1) ? Bq[q >> 1].y : Bq[q >> 1].x;
            ull Cv = (q & 1) ? Cq[q >> 1].y : Cq[q >> 1].x;
            h2[q] = fma2p(a2, h2[q], mul2p(dxp, Bv));
            y2 = fma2p(h2[q], Cv, y2);
        }
        float ylo, yhi;
        p2f(y2, ylo, yhi);
        out[(size_t)(rbase + s) * DD + d] = fmaf(xv, Dv, ylo + yhi);
        dl = dln; xv = xvn;
    }
}

// ---------------------------------------------------------------------------
extern "C" void kernel_launch(void* const* d_in, const int* in_sizes, int n_in,
                              void* d_out, int out_size) {
    const float* x     = (const float*)d_in[0];
    const float* A_log = (const float*)d_in[1];
    const float* Dw    = (const float*)d_in[2];
    const float* wx    = (const float*)d_in[3];
    const float* wdt   = (const float*)d_in[4];
    const float* bias  = (const float*)d_in[5];
    float* out = (float*)d_out;

    dim3 g1(NROW / 64, 2);
    k_gemm1<<<g1, 256>>>(x, wx);

    dim3 g2(DD / 64, NROW / 64);
    k_gemm2<<<g2, 256>>>(wdt, bias);

    dim3 gs(DD / 128, NC, BB);
    k_scan1<<<gs, 128>>>(x, A_log);

    k_combA<<<(BB * SC * DDNS) / 256, 256>>>();
    k_combB<<<(BB * DDNS) / 256, 256>>>();
    k_combC<<<(BB * SC * DDNS) / 256, 256>>>();

    k_scan2<<<gs, 128>>>(x, A_log, Dw, out);
}